// round 6
// baseline (speedup 1.0000x reference)
#include <cuda_runtime.h>

// CRF loss forward, B=512, N=1024, K=64, sm_100a.
// 4 independent chains per block, one per warp (warps map to distinct SMSPs).
// Per-warp: lane owns states 2l, 2l+1; linear-domain scan, register-resident
// exp(trans), f32x2 FMAs, exp(emit) one step ahead, branchless body,
// R1-exact renorm (warp-max every 4 steps, divide, double c2 += lg2f).

typedef unsigned long long ull;
#define FULLMASK 0xffffffffu

__device__ __forceinline__ void fma2(ull &d, ull a, ull b) {
    asm("fma.rn.f32x2 %0, %1, %2, %0;" : "+l"(d) : "l"(a), "l"(b));
}
__device__ __forceinline__ ull pack2(float x, float y) {
    ull r; asm("mov.b64 %0, {%1, %2};" : "=l"(r) : "f"(x), "f"(y)); return r;
}
__device__ __forceinline__ void unpack2(ull v, float &x, float &y) {
    asm("mov.b64 {%0, %1}, %2;" : "=f"(x), "=f"(y) : "l"(v));
}
__device__ __forceinline__ float ex2f(float x) {
    float r; asm("ex2.approx.f32 %0, %1;" : "=f"(r) : "f"(x)); return r;
}
__device__ __forceinline__ float lg2f(float x) {
    float r; asm("lg2.approx.f32 %0, %1;" : "=f"(r) : "f"(x)); return r;
}

__global__ __launch_bounds__(128) void crf_fwd_kernel(
    const float* __restrict__ y_pred,   // [B, N, K]
    const float* __restrict__ trans,    // [K, K]
    const int*   __restrict__ y_true,   // [B, N]
    float*       __restrict__ out)      // [B]
{
    constexpr int N = 1024;
    constexpr int K = 64;
    constexpr float LOG2E = 1.4426950408889634f;

    const int tid  = threadIdx.x;
    const int w    = tid >> 5;          // warp in block -> SMSP w
    const int lane = tid & 31;
    const int b    = blockIdx.x * 4 + w;   // chain handled by this warp
    const int j0   = 2 * lane, j1 = j0 + 1;

    __shared__ ull sh_a_all[4][2][32];  // per-warp double-buffered alpha
    ull (*sh_a)[32] = sh_a_all[w];

    // ---- E = exp(trans) columns j0, j1 in registers, paired over i ----
    ull Er0[32], Er1[32];
    #pragma unroll
    for (int p = 0; p < 32; p++) {
        float t00 = __ldg(&trans[(2 * p)     * K + j0]);
        float t01 = __ldg(&trans[(2 * p + 1) * K + j0]);
        float t10 = __ldg(&trans[(2 * p)     * K + j1]);
        float t11 = __ldg(&trans[(2 * p + 1) * K + j1]);
        Er0[p] = pack2(ex2f(t00 * LOG2E), ex2f(t01 * LOG2E));
        Er1[p] = pack2(ex2f(t10 * LOG2E), ex2f(t11 * LOG2E));
    }

    const float2* emrow = (const float2*)y_pred + (size_t)b * N * 32;
    const int*    ytrow = y_true + (size_t)b * N;

    // ---- t = 0 init ----
    float  pt = 0.f;
    double c2;           // log2-units scale accumulator
    int    ytprev;
    bool   pm;
    float  s0p, s1p;     // lane's own alpha pair (register copy)
    {
        float2 v = emrow[lane];
        bool okl = (v.x > -1e6f) & (v.y > -1e6f);
        bool ok0 = __all_sync(FULLMASK, okl);
        float mv0 = ok0 ? v.x : 0.f;
        float mv1 = ok0 ? v.y : 0.f;
        float mx = fmaxf(mv0, mv1);
        #pragma unroll
        for (int o = 16; o; o >>= 1) mx = fmaxf(mx, __shfl_xor_sync(FULLMASK, mx, o));
        s0p = ex2f((mv0 - mx) * LOG2E);
        s1p = ex2f((mv1 - mx) * LOG2E);
        c2 = (double)mx * 1.4426950408889634;
        ytprev = ytrow[0];
        if (ok0 && (ytprev >> 1) == lane) pt += (ytprev & 1) ? v.y : v.x;
        pm = ok0;
        sh_a[0][lane] = pack2(s0p, s1p);
    }
    __syncwarp();

    // ---- prefetch ring (depth 4) + exp-ahead ----
    float2 rem[4]; int ryt[4];
    #pragma unroll
    for (int k = 0; k < 4; k++) {
        rem[k] = __ldcs(&emrow[(1 + k) * 32 + lane]);
        ryt[k] = __ldg(&ytrow[1 + k]);
    }
    float2 enext;
    enext.x = ex2f(rem[0].x * LOG2E);
    enext.y = ex2f(rem[0].y * LOG2E);

    int buf = 0;

    // one scan step; SLOT = (T-1)&3 (compile-time constant); RENORM compile-time
    #define STEP(T, SLOT, RENORM)                                              \
    {                                                                          \
        const int t  = (T);                                                    \
        const int sl = (SLOT);                                                 \
        float em0 = rem[sl].x, em1 = rem[sl].y;                                \
        int   yt  = ryt[sl];                                                   \
        float2 ecur = enext;                                                   \
        float2 nxt  = rem[(sl + 1) & 3];                                       \
        enext.x = ex2f(nxt.x * LOG2E);                                         \
        enext.y = ex2f(nxt.y * LOG2E);                                         \
        int tf = t + 4; tf = (tf > N - 1) ? (N - 1) : tf;                      \
        rem[sl] = __ldcs(&emrow[tf * 32 + lane]);                              \
        ryt[sl] = __ldg(&ytrow[tf]);                                           \
        bool ok = __all_sync(FULLMASK, (em0 > -1e6f) & (em1 > -1e6f));         \
        const ulonglong2* ap = (const ulonglong2*)sh_a[buf];                   \
        ull A0 = 0ull, A1 = 0ull, B0 = 0ull, B1 = 0ull;                        \
        _Pragma("unroll")                                                      \
        for (int q = 0; q < 8; q++) {                                          \
            ulonglong2 v0 = ap[2 * q];                                         \
            ulonglong2 v1 = ap[2 * q + 1];                                     \
            fma2(A0, v0.x, Er0[4 * q]);                                        \
            fma2(B0, v0.x, Er1[4 * q]);                                        \
            fma2(A1, v0.y, Er0[4 * q + 1]);                                    \
            fma2(B1, v0.y, Er1[4 * q + 1]);                                    \
            fma2(A0, v1.x, Er0[4 * q + 2]);                                    \
            fma2(B0, v1.x, Er1[4 * q + 2]);                                    \
            fma2(A1, v1.y, Er0[4 * q + 3]);                                    \
            fma2(B1, v1.y, Er1[4 * q + 3]);                                    \
        }                                                                      \
        float xa, ya, xb, yb, xc, yc, xd, yd;                                  \
        unpack2(A0, xa, ya); unpack2(A1, xb, yb);                              \
        unpack2(B0, xc, yc); unpack2(B1, xd, yd);                              \
        float s0n = ((xa + xb) + (ya + yb)) * ecur.x;                          \
        float s1n = ((xc + xd) + (yc + yd)) * ecur.y;                          \
        float s0 = ok ? s0n : s0p;                                             \
        float s1 = ok ? s1n : s1p;                                             \
        if (ok && (yt >> 1) == lane) {                                         \
            pt += (yt & 1) ? em1 : em0;                                        \
            if (pm) pt += __ldg(&trans[ytprev * K + yt]);                      \
        }                                                                      \
        pm = ok; ytprev = yt;                                                  \
        if (RENORM) {                                                          \
            float r = fmaxf(s0, s1);                                           \
            _Pragma("unroll")                                                  \
            for (int o = 16; o; o >>= 1)                                       \
                r = fmaxf(r, __shfl_xor_sync(FULLMASK, r, o));                 \
            float inv = 1.0f / r;                                              \
            s0 *= inv; s1 *= inv;                                              \
            c2 += (double)lg2f(r);                                             \
        }                                                                      \
        s0p = s0; s1p = s1;                                                    \
        sh_a[buf ^ 1][lane] = pack2(s0, s1);                                   \
        buf ^= 1;                                                              \
        __syncwarp();                                                          \
    }

    // 255 groups of 4 (t = 1 .. 1020), renorm on last step of each group
    for (int g = 0; g < 255; g++) {
        const int tb = 1 + 4 * g;
        STEP(tb + 0, 0, false)
        STEP(tb + 1, 1, false)
        STEP(tb + 2, 2, false)
        STEP(tb + 3, 3, true)
    }
    // tail: t = 1021, 1022, 1023 (constant slots, no renorm)
    STEP(1021, 0, false)
    STEP(1022, 1, false)
    STEP(1023, 2, false)
    #undef STEP

    // ---- finalize: log_norm - target_score ----
    float ssum = s0p + s1p;
    #pragma unroll
    for (int o = 16; o; o >>= 1) {
        ssum += __shfl_xor_sync(FULLMASK, ssum, o);
        pt   += __shfl_xor_sync(FULLMASK, pt,   o);
    }
    if (lane == 0) {
        double lognorm = (c2 + (double)lg2f(ssum)) * 0.6931471805599453;
        out[b] = (float)(lognorm - (double)pt);
    }
}

extern "C" void kernel_launch(void* const* d_in, const int* in_sizes, int n_in,
                              void* d_out, int out_size) {
    const float* y_pred = (const float*)d_in[0];
    const float* trans  = (const float*)d_in[1];
    const int*   y_true = (const int*)d_in[2];
    float* out = (float*)d_out;

    const int B = in_sizes[2] / 1024;   // 512
    crf_fwd_kernel<<<B / 4, 128>>>(y_pred, trans, y_true, out);
}